// round 3
// baseline (speedup 1.0000x reference)
#include <cuda_runtime.h>

#define TT 100
#define BB 512
#define NIN 784
#define HH 1024
#define OO 10

#define BETA    0.95f
#define DECAY   0.05f
#define A_PLUS  0.01f
#define A_MINUS 0.01f

#define MW0 25   // 784 bits -> 25 words (last word uses 16 bits)
#define MW1 32   // 1024 bits -> 32 words

// Output layout (flattened tuple, each [T,B,dim] row-major):
// spk0, pre0, post0 | spk1, pre1, post1 | spk2, mem2, pre2, post2
#define SZ0 ((size_t)TT * BB * NIN)   // 40,140,800
#define SZ1 ((size_t)TT * BB * HH)    // 52,428,800
#define SZ2 ((size_t)TT * BB * OO)    // 512,000

// Scratch (no allocations allowed -> device globals)
__device__ unsigned int g_mask0[(size_t)TT * BB * MW0];  // 5.12 MB
__device__ unsigned int g_mask1[(size_t)TT * BB * MW1];  // 6.55 MB
__device__ float        g_S1[HH];
__device__ float        g_cur2[(size_t)TT * BB * OO];    // 2 MB

// ---------------------------------------------------------------------------
// Kernel S1: row sums of W1  (S1[h] = sum_n W1[h,n])
// ---------------------------------------------------------------------------
__global__ void k_s1(const float* __restrict__ W1) {
    int h    = (blockIdx.x * blockDim.x + threadIdx.x) >> 5;
    int lane = threadIdx.x & 31;
    if (h >= HH) return;
    float s = 0.f;
    for (int n = lane; n < NIN; n += 32) s += W1[(size_t)h * NIN + n];
    #pragma unroll
    for (int d = 16; d; d >>= 1) s += __shfl_xor_sync(0xffffffffu, s, d);
    if (lane == 0) g_S1[h] = s;
}

// ---------------------------------------------------------------------------
// Kernel 1: layer-0 scan over T per (b,n). thr=0, subtract-reset => mem
// unchanged by reset. Writes spk0/pre0/post0 and spike bitmask.
// 800 threads per b (25 warps) so warps align with 32-bit mask words.
// ---------------------------------------------------------------------------
__global__ void k_layer0(const float* __restrict__ x, float* __restrict__ out) {
    int gid  = blockIdx.x * 256 + threadIdx.x;
    int b    = gid / 800;
    int j    = gid - b * 800;      // padded n index
    int lane = threadIdx.x & 31;
    bool valid = (j < NIN);

    float mem = 0.f, pre = 0.f, post = 0.f;
    const float* xp     = x + (size_t)b * NIN + j;
    float*       o_spk  = out + (size_t)b * NIN + j;
    float*       o_pre  = o_spk + SZ0;
    float*       o_post = o_spk + 2 * SZ0;
    unsigned int* mrow  = g_mask0 + (size_t)b * MW0 + (j >> 5);

    for (int t = 0; t < TT; t++) {
        float xv = valid ? xp[(size_t)t * BB * NIN] : 0.f;
        mem = BETA * mem + xv;                 // thr=0 -> subtract-reset is a no-op
        bool s = (mem > 0.f) && valid;
        unsigned int w = __ballot_sync(0xffffffffu, s);
        if (lane == 0) mrow[(size_t)t * BB * MW0] = w;
        if (valid) {
            float fs = s ? 1.f : 0.f;
            pre  = (pre  - DECAY * pre)  + A_PLUS  * fs;
            post = (post - DECAY * post) - A_MINUS * fs;
            size_t off = (size_t)t * BB * NIN;
            o_spk[off]  = fs;
            o_pre[off]  = pre;
            o_post[off] = post;
        }
    }
}

// ---------------------------------------------------------------------------
// Kernel 2: layer-1 scan. cur1[t,b,h] = relu(S1[h] - sum_{zero bits} W1[h,n]).
// Zero-reset LIF + traces. Block = (b, 256-wide h chunk).
// Fast path: spk0 all-ones (expected nearly always) -> corr = 0, cur = S1[h].
// ---------------------------------------------------------------------------
__global__ void k_layer1(const float* __restrict__ W1,
                         const float* __restrict__ thr1,
                         float* __restrict__ out) {
    __shared__ unsigned int sm[MW0];
    __shared__ unsigned int sfull;

    int b  = blockIdx.x >> 2;
    int hc = blockIdx.x & 3;
    int h  = hc * 256 + threadIdx.x;
    int lane = threadIdx.x & 31;

    float s1  = g_S1[h];
    float thr = thr1[h];
    const float* w1row = W1 + (size_t)h * NIN;
    float mem = 0.f, pre = 0.f, post = 0.f;
    bool  spk_prev = false;

    float* o_spk  = out + 3 * SZ0 + (size_t)b * HH + h;
    float* o_pre  = o_spk + SZ1;
    float* o_post = o_spk + 2 * SZ1;
    const unsigned int* m0   = g_mask0 + (size_t)b * MW0;
    unsigned int*       m1w  = g_mask1 + (size_t)b * MW1 + (h >> 5);

    for (int t = 0; t < TT; t++) {
        // warp 0 loads this (t,b) mask row + computes all-ones flag
        if (threadIdx.x < 32) {
            unsigned int w  = 0xFFFFFFFFu;
            if (threadIdx.x < MW0) w = m0[(size_t)t * BB * MW0 + threadIdx.x];
            unsigned int vm = (threadIdx.x == MW0 - 1) ? 0xFFFFu : 0xFFFFFFFFu;
            bool full = ((w & vm) == vm);
            unsigned int bal = __ballot_sync(0xffffffffu, full);
            if (threadIdx.x < MW0) sm[threadIdx.x] = w;
            if (threadIdx.x == 0)  sfull = (bal == 0xFFFFFFFFu) ? 1u : 0u;
        }
        __syncthreads();

        float corr = 0.f;
        if (!sfull) {                       // rare path: some spk0 == 0
            #pragma unroll 1
            for (int wd = 0; wd < MW0; wd++) {
                unsigned int vm = (wd == MW0 - 1) ? 0xFFFFu : 0xFFFFFFFFu;
                unsigned int z  = (~sm[wd]) & vm;
                while (z) {
                    int bt = __ffs(z) - 1; z &= z - 1;
                    corr += __ldg(w1row + wd * 32 + bt);
                }
            }
        }
        __syncthreads();

        float cur = s1 - corr;
        cur = cur > 0.f ? cur : 0.f;        // relu
        float base = BETA * mem + cur;
        mem = spk_prev ? 0.f : base;        // zero reset (reset = prev mem > thr)
        bool s = (mem - thr) > 0.f;
        spk_prev = s;

        float fs = s ? 1.f : 0.f;
        pre  = (pre  - DECAY * pre)  + A_PLUS  * fs;
        post = (post - DECAY * post) - A_MINUS * fs;

        unsigned int w1m = __ballot_sync(0xffffffffu, s);
        if (lane == 0) m1w[(size_t)t * BB * MW1] = w1m;

        size_t off = (size_t)t * BB * HH;
        o_spk[off]  = fs;
        o_pre[off]  = pre;
        o_post[off] = post;
    }
}

// ---------------------------------------------------------------------------
// Kernel 3: cur2[m,o] = sum_{h: spk1[m,h]=1} W2[o,h]  (bitmask gather GEMM).
// One warp per row m; lane L owns mask word L (h = 32L + bit). W2 in SMEM.
// ---------------------------------------------------------------------------
__global__ void k_cur2(const float* __restrict__ W2) {
    __shared__ float sW2[OO * HH];   // 40 KB
    for (int i = threadIdx.x; i < OO * HH; i += blockDim.x) sW2[i] = W2[i];
    __syncthreads();

    int wid  = threadIdx.x >> 5;
    int lane = threadIdx.x & 31;

    for (int m = blockIdx.x * 8 + wid; m < TT * BB; m += 800 * 8) {
        unsigned int w = g_mask1[(size_t)m * MW1 + lane];
        float acc[OO];
        #pragma unroll
        for (int o = 0; o < OO; o++) acc[o] = 0.f;
        while (w) {
            int bt = __ffs(w) - 1; w &= w - 1;
            int hh = lane * 32 + bt;
            #pragma unroll
            for (int o = 0; o < OO; o++) acc[o] += sW2[o * HH + hh];
        }
        #pragma unroll
        for (int o = 0; o < OO; o++) {
            float v = acc[o];
            #pragma unroll
            for (int d = 16; d; d >>= 1) v += __shfl_xor_sync(0xffffffffu, v, d);
            if (lane == o) g_cur2[(size_t)m * OO + o] = v;
        }
    }
}

// ---------------------------------------------------------------------------
// Kernel 4: layer-2 scan per (b,o). Writes spk2, mem2, pre2, post2.
// ---------------------------------------------------------------------------
__global__ void k_layer2(const float* __restrict__ thr2, float* __restrict__ out) {
    int idx = blockIdx.x * 256 + threadIdx.x;
    if (idx >= BB * OO) return;
    int o = idx % OO;

    float thr = thr2[o];
    float mem = 0.f, pre = 0.f, post = 0.f;
    bool  spk_prev = false;

    float* obase = out + 3 * SZ0 + 3 * SZ1 + idx;   // idx == b*OO + o
    for (int t = 0; t < TT; t++) {
        float cur = g_cur2[(size_t)t * BB * OO + idx];
        cur = cur > 0.f ? cur : 0.f;                // relu
        float base = BETA * mem + cur;
        mem = spk_prev ? 0.f : base;
        bool s = (mem - thr) > 0.f;
        spk_prev = s;
        float fs = s ? 1.f : 0.f;
        pre  = (pre  - DECAY * pre)  + A_PLUS  * fs;
        post = (post - DECAY * post) - A_MINUS * fs;

        size_t off = (size_t)t * BB * OO;
        obase[off]           = fs;    // spk2
        obase[SZ2 + off]     = mem;   // mem2
        obase[2 * SZ2 + off] = pre;   // pre2
        obase[3 * SZ2 + off] = post;  // post2
    }
}

// ---------------------------------------------------------------------------
extern "C" void kernel_launch(void* const* d_in, const int* in_sizes, int n_in,
                              void* d_out, int out_size) {
    const float* x    = (const float*)d_in[0];
    const float* W1   = (const float*)d_in[1];
    const float* W2   = (const float*)d_in[2];
    const float* thr1 = (const float*)d_in[3];
    const float* thr2 = (const float*)d_in[4];
    float* out = (float*)d_out;

    k_s1    <<<128, 256>>>(W1);
    k_layer0<<<(BB * 800) / 256, 256>>>(x, out);
    k_layer1<<<BB * 4, 256>>>(W1, thr1, out);
    k_cur2  <<<800, 256>>>(W2);
    k_layer2<<<(BB * OO + 255) / 256, 256>>>(thr2, out);
}

// round 5
// speedup vs baseline: 1.1025x; 1.1025x over previous
#include <cuda_runtime.h>

#define TT 100
#define BB 512
#define NIN 784
#define HH 1024
#define OO 10

#define BETA    0.95f
#define DECAY   0.05f
#define A_PLUS  0.01f
#define A_MINUS 0.01f

#define MW0 25   // 784 bits -> 25 words (last word uses 16 bits)
#define MW1 32   // 1024 bits -> 32 words

// Output layout (flattened tuple, each [T,B,dim] row-major):
// spk0, pre0, post0 | spk1, pre1, post1 | spk2, mem2, pre2, post2
#define SZ0 ((size_t)TT * BB * NIN)   // 40,140,800
#define SZ1 ((size_t)TT * BB * HH)    // 52,428,800
#define SZ2 ((size_t)TT * BB * OO)    // 512,000

// Scratch (no allocations allowed -> device globals)
__device__ unsigned int g_mask1[(size_t)TT * BB * MW1];  // 6.55 MB
__device__ float        g_S1[HH];
__device__ float        g_cur2[(size_t)TT * BB * OO];    // 2 MB

// ---------------------------------------------------------------------------
// Kernel S1: row sums of W1  (S1[h] = sum_n W1[h,n])
// ---------------------------------------------------------------------------
__global__ void k_s1(const float* __restrict__ W1) {
    int h    = (blockIdx.x * blockDim.x + threadIdx.x) >> 5;
    int lane = threadIdx.x & 31;
    if (h >= HH) return;
    float s = 0.f;
    for (int n = lane; n < NIN; n += 32) s += W1[(size_t)h * NIN + n];
    #pragma unroll
    for (int d = 16; d; d >>= 1) s += __shfl_xor_sync(0xffffffffu, s, d);
    if (lane == 0) g_S1[h] = s;
}

// ---------------------------------------------------------------------------
// Fused layer0 + layer1 scan. One block per batch element b, 1024 threads.
// Thread tid plays two roles: input index j = tid (valid j < 784) for layer 0,
// and hidden unit h = tid for layer 1. mask0 stays in SMEM (never hits HBM).
//
// Layer 0: thr=0, subtract-reset is a no-op on mem. spk0 = (mem0 > 0).
// Layer 1: cur1[h] = relu(S1[h] - sum_{n: spk0[n]=0} W1[h,n]).
//          Fast path (spk0 all-ones, expected almost always): cur1 = S1[h].
// ---------------------------------------------------------------------------
__global__ void __launch_bounds__(1024)
k_fused01(const float* __restrict__ x,
          const float* __restrict__ W1,
          const float* __restrict__ thr1,
          float* __restrict__ out) {
    __shared__ unsigned int sm[MW0];
    __shared__ unsigned int sfull;

    int b    = blockIdx.x;
    int tid  = threadIdx.x;          // 0..1023
    int lane = tid & 31;
    int wid  = tid >> 5;
    bool v0  = (tid < NIN);

    // layer-0 state
    float mem0 = 0.f, pre0 = 0.f, post0 = 0.f;
    // layer-1 state (h = tid)
    float s1  = g_S1[tid];
    float thr = thr1[tid];
    const float* w1row = W1 + (size_t)tid * NIN;
    float mem1 = 0.f, pre1 = 0.f, post1 = 0.f;
    bool  spk_prev = false;

    const float* xp = x + (size_t)b * NIN + tid;
    float* o0 = out + (size_t)b * NIN + tid;                 // layer-0 outputs
    float* o1 = out + 3 * SZ0 + (size_t)b * HH + tid;        // layer-1 outputs
    unsigned int* m1w = g_mask1 + (size_t)b * MW1 + wid;     // lane0 writes

    for (int t = 0; t < TT; t++) {
        // ---- layer 0 ----
        float xv = v0 ? xp[(size_t)t * BB * NIN] : 0.f;
        mem0 = BETA * mem0 + xv;
        bool s0 = (mem0 > 0.f) && v0;
        unsigned int w0 = __ballot_sync(0xffffffffu, s0);
        if (lane == 0 && wid < MW0) sm[wid] = w0;
        if (v0) {
            float fs = s0 ? 1.f : 0.f;
            pre0  = (pre0  - DECAY * pre0)  + A_PLUS  * fs;
            post0 = (post0 - DECAY * post0) - A_MINUS * fs;
            size_t off = (size_t)t * BB * NIN;
            o0[off]           = fs;
            o0[SZ0 + off]     = pre0;
            o0[2 * SZ0 + off] = post0;
        }
        __syncthreads();

        // warp 0 computes the all-ones flag
        if (tid < 32) {
            unsigned int w  = 0xFFFFFFFFu;
            if (tid < MW0) w = sm[tid];
            unsigned int vm = (tid == MW0 - 1) ? 0xFFFFu : 0xFFFFFFFFu;
            unsigned int bal = __ballot_sync(0xffffffffu, (w & vm) == vm);
            if (tid == 0) sfull = (bal == 0xFFFFFFFFu) ? 1u : 0u;
        }
        __syncthreads();

        // ---- layer 1 ----
        float corr = 0.f;
        bool slow = (sfull == 0u);     // block-uniform
        if (slow) {
            #pragma unroll 1
            for (int wd = 0; wd < MW0; wd++) {
                unsigned int vm = (wd == MW0 - 1) ? 0xFFFFu : 0xFFFFFFFFu;
                unsigned int z  = (~sm[wd]) & vm;
                while (z) {
                    int bt = __ffs(z) - 1; z &= z - 1;
                    corr += __ldg(w1row + wd * 32 + bt);
                }
            }
        }

        float cur = s1 - corr;
        cur = cur > 0.f ? cur : 0.f;       // relu
        float base = BETA * mem1 + cur;
        mem1 = spk_prev ? 0.f : base;      // zero reset (reset = prev mem > thr)
        bool s = (mem1 - thr) > 0.f;
        spk_prev = s;

        float fs = s ? 1.f : 0.f;
        pre1  = (pre1  - DECAY * pre1)  + A_PLUS  * fs;
        post1 = (post1 - DECAY * post1) - A_MINUS * fs;

        unsigned int w1m = __ballot_sync(0xffffffffu, s);
        if (lane == 0) m1w[(size_t)t * BB * MW1] = w1m;

        size_t off = (size_t)t * BB * HH;
        o1[off]           = fs;
        o1[SZ1 + off]     = pre1;
        o1[2 * SZ1 + off] = post1;

        // protect sm[] against next iteration's overwrite (block-uniform cond)
        if (slow) __syncthreads();
    }
}

// ---------------------------------------------------------------------------
// k_cur2: cur2[m,o] = sum_{h: spk1[m,h]=1} W2[o,h]  (bitmask gather GEMM).
// One warp per row m. Conflict-free: lane L owns BIT L of each mask word
// (word broadcast via shfl), so SMEM loads sW2[o*HH + wd*32 + lane] have
// lane-stride 1 -> no bank conflicts (the R3 version had 32-way conflicts).
// ---------------------------------------------------------------------------
__global__ void k_cur2(const float* __restrict__ W2) {
    __shared__ float sW2[OO * HH];   // 40 KB, o-major
    for (int i = threadIdx.x; i < OO * HH; i += blockDim.x) sW2[i] = W2[i];
    __syncthreads();

    int wid  = threadIdx.x >> 5;
    int lane = threadIdx.x & 31;
    const int NWARP = 8;             // 256 threads

    for (int m = blockIdx.x * NWARP + wid; m < TT * BB; m += gridDim.x * NWARP) {
        unsigned int myw = g_mask1[(size_t)m * MW1 + lane];  // lane L holds word L
        float acc[OO];
        #pragma unroll
        for (int o = 0; o < OO; o++) acc[o] = 0.f;

        #pragma unroll 4
        for (int wd = 0; wd < MW1; wd++) {
            unsigned int word = __shfl_sync(0xffffffffu, myw, wd);
            if (word == 0u) continue;                 // warp-uniform skip
            const float* p = &sW2[wd * 32 + lane];
            if (word == 0xFFFFFFFFu) {
                #pragma unroll
                for (int o = 0; o < OO; o++) acc[o] += p[o * HH];
            } else {
                bool bit = (word >> lane) & 1u;
                float f = bit ? 1.f : 0.f;
                #pragma unroll
                for (int o = 0; o < OO; o++) acc[o] += f * p[o * HH];
            }
        }
        #pragma unroll
        for (int o = 0; o < OO; o++) {
            float v = acc[o];
            #pragma unroll
            for (int d = 16; d; d >>= 1) v += __shfl_xor_sync(0xffffffffu, v, d);
            if (lane == o) g_cur2[(size_t)m * OO + o] = v;
        }
    }
}

// ---------------------------------------------------------------------------
// Kernel 4: layer-2 scan per (b,o). Writes spk2, mem2, pre2, post2.
// ---------------------------------------------------------------------------
__global__ void k_layer2(const float* __restrict__ thr2, float* __restrict__ out) {
    int idx = blockIdx.x * 256 + threadIdx.x;
    if (idx >= BB * OO) return;
    int o = idx % OO;

    float thr = thr2[o];
    float mem = 0.f, pre = 0.f, post = 0.f;
    bool  spk_prev = false;

    float* obase = out + 3 * SZ0 + 3 * SZ1 + idx;   // idx == b*OO + o
    for (int t = 0; t < TT; t++) {
        float cur = g_cur2[(size_t)t * BB * OO + idx];
        cur = cur > 0.f ? cur : 0.f;                // relu
        float base = BETA * mem + cur;
        mem = spk_prev ? 0.f : base;
        bool s = (mem - thr) > 0.f;
        spk_prev = s;
        float fs = s ? 1.f : 0.f;
        pre  = (pre  - DECAY * pre)  + A_PLUS  * fs;
        post = (post - DECAY * post) - A_MINUS * fs;

        size_t off = (size_t)t * BB * OO;
        obase[off]           = fs;    // spk2
        obase[SZ2 + off]     = mem;   // mem2
        obase[2 * SZ2 + off] = pre;   // pre2
        obase[3 * SZ2 + off] = post;  // post2
    }
}

// ---------------------------------------------------------------------------
extern "C" void kernel_launch(void* const* d_in, const int* in_sizes, int n_in,
                              void* d_out, int out_size) {
    const float* x    = (const float*)d_in[0];
    const float* W1   = (const float*)d_in[1];
    const float* W2   = (const float*)d_in[2];
    const float* thr1 = (const float*)d_in[3];
    const float* thr2 = (const float*)d_in[4];
    float* out = (float*)d_out;

    k_s1     <<<128, 256>>>(W1);
    k_fused01<<<BB, 1024>>>(x, W1, thr1, out);
    k_cur2   <<<1600, 256>>>(W2);
    k_layer2 <<<(BB * OO + 255) / 256, 256>>>(thr2, out);
}

// round 6
// speedup vs baseline: 1.2670x; 1.1492x over previous
#include <cuda_runtime.h>

#define TT 100
#define BB 512
#define NIN 784
#define HH 1024
#define OO 10

#define BETA    0.95f
#define DECAY   0.05f
#define A_PLUS  0.01f
#define A_MINUS 0.01f

#define MW0 25   // 784 bits -> 25 words (last word: 16 valid bits)
#define MW1 32   // 1024 bits -> 32 words

// Output layout (flattened tuple, each [T,B,dim] row-major):
// spk0, pre0, post0 | spk1, pre1, post1 | spk2, mem2, pre2, post2
#define SZ0 ((size_t)TT * BB * NIN)
#define SZ1 ((size_t)TT * BB * HH)
#define SZ2 ((size_t)TT * BB * OO)

// Scratch (no allocations allowed -> device globals)
__device__ unsigned int g_mask0[(size_t)TT * BB * MW0];  // 5.12 MB  [t][b][w]
__device__ unsigned int g_mask1[(size_t)TT * BB * MW1];  // 6.55 MB  [t][b][w]
__device__ float        g_S1[HH];
__device__ float        g_cur2[(size_t)TT * BB * OO];    // 2 MB

// Spread 8 bits of x into every 4th bit of a 32-bit word (Morton-4).
__device__ __forceinline__ unsigned int spread8(unsigned int x) {
    x &= 0xFFu;
    x = (x | (x << 12)) & 0x000F000Fu;
    x = (x | (x << 6))  & 0x03030303u;
    x = (x | (x << 3))  & 0x11111111u;
    return x;
}

// Pack 4 per-bit ballots into this lane's mask word (lane j produces word j of
// the warp, bits h = 128*W + 32*j + 4*L' + k  <-  bit (8j+L') of bal_k).
__device__ __forceinline__ unsigned int pack_word(unsigned int b0, unsigned int b1,
                                                  unsigned int b2, unsigned int b3,
                                                  int j) {
    return  spread8(b0 >> (8 * j))
         | (spread8(b1 >> (8 * j)) << 1)
         | (spread8(b2 >> (8 * j)) << 2)
         | (spread8(b3 >> (8 * j)) << 3);
}

// ---------------------------------------------------------------------------
// S1[h] = sum_n W1[h,n]
// ---------------------------------------------------------------------------
__global__ void k_s1(const float* __restrict__ W1) {
    int h    = (blockIdx.x * blockDim.x + threadIdx.x) >> 5;
    int lane = threadIdx.x & 31;
    if (h >= HH) return;
    float s = 0.f;
    for (int n = lane; n < NIN; n += 32) s += W1[(size_t)h * NIN + n];
    #pragma unroll
    for (int d = 16; d; d >>= 1) s += __shfl_xor_sync(0xffffffffu, s, d);
    if (lane == 0) g_S1[h] = s;
}

// ---------------------------------------------------------------------------
// Layer 0, vectorized x4. One block per b (256 thr, 196 valid x 4 inputs).
// thr=0 & subtract-reset => mem unchanged by reset. No shared mem, no barriers.
// Mask words built from 4 ballots + bit-spread on lanes 0-3 of each warp.
// ---------------------------------------------------------------------------
__global__ void __launch_bounds__(256)
k_l0(const float* __restrict__ x, float* __restrict__ out) {
    int b    = blockIdx.x;
    int tid  = threadIdx.x;
    int lane = tid & 31;
    int wrp  = tid >> 5;
    bool v0  = (tid < NIN / 4);          // 196 valid threads
    int  j0  = tid * 4;

    float4 mem = {0,0,0,0}, pre = {0,0,0,0}, post = {0,0,0,0};

    const float4* xp = (const float4*)(x + (size_t)b * NIN) + tid;
    float4* o_spk  = (float4*)(out + (size_t)b * NIN) + tid;
    float4* o_pre  = (float4*)(out + SZ0     + (size_t)b * NIN) + tid;
    float4* o_post = (float4*)(out + 2 * SZ0 + (size_t)b * NIN) + tid;
    unsigned int* mrow = g_mask0 + (size_t)b * MW0;
    (void)j0;

    const size_t xstride = (size_t)BB * NIN / 4;   // float4 stride per t

    for (int t = 0; t < TT; t++) {
        float4 xv = {0,0,0,0};
        if (v0) xv = xp[t * xstride];
        mem.x = BETA * mem.x + xv.x;
        mem.y = BETA * mem.y + xv.y;
        mem.z = BETA * mem.z + xv.z;
        mem.w = BETA * mem.w + xv.w;
        bool s0 = v0 && (mem.x > 0.f);
        bool s1b = v0 && (mem.y > 0.f);
        bool s2 = v0 && (mem.z > 0.f);
        bool s3 = v0 && (mem.w > 0.f);

        unsigned int b0 = __ballot_sync(0xffffffffu, s0);
        unsigned int b1 = __ballot_sync(0xffffffffu, s1b);
        unsigned int b2 = __ballot_sync(0xffffffffu, s2);
        unsigned int b3 = __ballot_sync(0xffffffffu, s3);
        if (lane < 4) {
            int widx = wrp * 4 + lane;
            if (widx < MW0)
                mrow[(size_t)t * BB * MW0 + widx] = pack_word(b0, b1, b2, b3, lane);
        }

        if (v0) {
            float4 fs = {s0 ? 1.f : 0.f, s1b ? 1.f : 0.f, s2 ? 1.f : 0.f, s3 ? 1.f : 0.f};
            pre.x  = (pre.x  - DECAY * pre.x)  + A_PLUS  * fs.x;
            pre.y  = (pre.y  - DECAY * pre.y)  + A_PLUS  * fs.y;
            pre.z  = (pre.z  - DECAY * pre.z)  + A_PLUS  * fs.z;
            pre.w  = (pre.w  - DECAY * pre.w)  + A_PLUS  * fs.w;
            post.x = (post.x - DECAY * post.x) - A_MINUS * fs.x;
            post.y = (post.y - DECAY * post.y) - A_MINUS * fs.y;
            post.z = (post.z - DECAY * post.z) - A_MINUS * fs.z;
            post.w = (post.w - DECAY * post.w) - A_MINUS * fs.w;
            o_spk [t * xstride] = fs;
            o_pre [t * xstride] = pre;
            o_post[t * xstride] = post;
        }
    }
}

// ---------------------------------------------------------------------------
// Layer 1, vectorized x4. One block per b (256 thr x 4 h = 1024). No barriers:
// each warp re-derives the spk0 all-ones flag from g_mask0 (lanes 0-24 load
// the 25 words; one ballot). Fast path (always in practice): cur1 = S1[h].
// Slow path: words come via shfl, gather W1 for zero bits.
// ---------------------------------------------------------------------------
__global__ void __launch_bounds__(256)
k_l1(const float* __restrict__ W1,
     const float* __restrict__ thr1,
     float* __restrict__ out) {
    int b    = blockIdx.x;
    int tid  = threadIdx.x;
    int lane = tid & 31;
    int wrp  = tid >> 5;
    int h0   = tid * 4;

    float4 s1v = ((const float4*)g_S1)[tid];
    float4 thr = ((const float4*)thr1)[tid];
    float4 mem = {0,0,0,0}, pre = {0,0,0,0}, post = {0,0,0,0};
    bool sp0 = false, sp1 = false, sp2 = false, sp3 = false;  // prev spikes

    float4* o_spk  = (float4*)(out + 3 * SZ0            + (size_t)b * HH) + tid;
    float4* o_pre  = (float4*)(out + 3 * SZ0 + SZ1      + (size_t)b * HH) + tid;
    float4* o_post = (float4*)(out + 3 * SZ0 + 2 * SZ1  + (size_t)b * HH) + tid;
    const unsigned int* m0 = g_mask0 + (size_t)b * MW0;
    unsigned int*      m1  = g_mask1 + (size_t)b * MW1;
    const size_t ostride = (size_t)BB * HH / 4;

    for (int t = 0; t < TT; t++) {
        // per-warp all-ones check on the spk0 mask (no cross-warp comm needed)
        unsigned int w  = 0xFFFFFFFFu;
        unsigned int vm = (lane == MW0 - 1) ? 0xFFFFu : 0xFFFFFFFFu;
        if (lane < MW0) w = __ldg(m0 + (size_t)t * BB * MW0 + lane);
        bool full = ((w & vm) == vm);
        bool allfull = (__ballot_sync(0xffffffffu, full) == 0xffffffffu);

        float4 cur = s1v;
        if (!allfull) {                          // rare path
            float c0 = 0.f, c1 = 0.f, c2 = 0.f, c3 = 0.f;
            #pragma unroll 1
            for (int wd = 0; wd < MW0; wd++) {
                unsigned int wv  = __shfl_sync(0xffffffffu, w, wd);
                unsigned int wvm = (wd == MW0 - 1) ? 0xFFFFu : 0xFFFFFFFFu;
                unsigned int z   = (~wv) & wvm;
                while (z) {
                    int bt = __ffs(z) - 1; z &= z - 1;
                    int n = wd * 32 + bt;
                    c0 += __ldg(W1 + (size_t)(h0 + 0) * NIN + n);
                    c1 += __ldg(W1 + (size_t)(h0 + 1) * NIN + n);
                    c2 += __ldg(W1 + (size_t)(h0 + 2) * NIN + n);
                    c3 += __ldg(W1 + (size_t)(h0 + 3) * NIN + n);
                }
            }
            cur.x -= c0; cur.y -= c1; cur.z -= c2; cur.w -= c3;
        }
        cur.x = cur.x > 0.f ? cur.x : 0.f;
        cur.y = cur.y > 0.f ? cur.y : 0.f;
        cur.z = cur.z > 0.f ? cur.z : 0.f;
        cur.w = cur.w > 0.f ? cur.w : 0.f;

        mem.x = sp0 ? 0.f : (BETA * mem.x + cur.x);
        mem.y = sp1 ? 0.f : (BETA * mem.y + cur.y);
        mem.z = sp2 ? 0.f : (BETA * mem.z + cur.z);
        mem.w = sp3 ? 0.f : (BETA * mem.w + cur.w);
        // note: zero-reset discards current input too: (beta*mem+cur)*(1-reset)
        // with reset = prev spike; implemented by zeroing BEFORE adding? No:
        // reference zeroes the NEW base when reset=1. mem_new = base*(1-reset).
        // base = beta*mem_prev + cur. Since reset==sp (prev spike), and when
        // sp==1 mem_prev was already the value that spiked... we must zero base:
        // mem = sp ? 0 : base.  (exactly what we did above)
        sp0 = (mem.x - thr.x) > 0.f;
        sp1 = (mem.y - thr.y) > 0.f;
        sp2 = (mem.z - thr.z) > 0.f;
        sp3 = (mem.w - thr.w) > 0.f;

        unsigned int b0 = __ballot_sync(0xffffffffu, sp0);
        unsigned int b1 = __ballot_sync(0xffffffffu, sp1);
        unsigned int b2 = __ballot_sync(0xffffffffu, sp2);
        unsigned int b3 = __ballot_sync(0xffffffffu, sp3);
        if (lane < 4)
            m1[(size_t)t * BB * MW1 + wrp * 4 + lane] = pack_word(b0, b1, b2, b3, lane);

        float4 fs = {sp0 ? 1.f : 0.f, sp1 ? 1.f : 0.f, sp2 ? 1.f : 0.f, sp3 ? 1.f : 0.f};
        pre.x  = (pre.x  - DECAY * pre.x)  + A_PLUS  * fs.x;
        pre.y  = (pre.y  - DECAY * pre.y)  + A_PLUS  * fs.y;
        pre.z  = (pre.z  - DECAY * pre.z)  + A_PLUS  * fs.z;
        pre.w  = (pre.w  - DECAY * pre.w)  + A_PLUS  * fs.w;
        post.x = (post.x - DECAY * post.x) - A_MINUS * fs.x;
        post.y = (post.y - DECAY * post.y) - A_MINUS * fs.y;
        post.z = (post.z - DECAY * post.z) - A_MINUS * fs.z;
        post.w = (post.w - DECAY * post.w) - A_MINUS * fs.w;

        o_spk [t * ostride] = fs;
        o_pre [t * ostride] = pre;
        o_post[t * ostride] = post;
    }
}

// ---------------------------------------------------------------------------
// cur2[m,o] = sum_{h: spk1[m,h]=1} W2[o,h]. One warp per row; lane L owns bit
// L of each word (broadcast via shfl) -> conflict-free SMEM loads.
// ---------------------------------------------------------------------------
__global__ void k_cur2(const float* __restrict__ W2) {
    __shared__ float sW2[OO * HH];   // 40 KB
    for (int i = threadIdx.x; i < OO * HH; i += blockDim.x) sW2[i] = W2[i];
    __syncthreads();

    int wid  = threadIdx.x >> 5;
    int lane = threadIdx.x & 31;
    const int NWARP = 8;

    for (int m = blockIdx.x * NWARP + wid; m < TT * BB; m += gridDim.x * NWARP) {
        unsigned int myw = g_mask1[(size_t)m * MW1 + lane];
        float acc[OO];
        #pragma unroll
        for (int o = 0; o < OO; o++) acc[o] = 0.f;

        #pragma unroll 4
        for (int wd = 0; wd < MW1; wd++) {
            unsigned int word = __shfl_sync(0xffffffffu, myw, wd);
            if (word == 0u) continue;
            const float* p = &sW2[wd * 32 + lane];
            if (word == 0xFFFFFFFFu) {
                #pragma unroll
                for (int o = 0; o < OO; o++) acc[o] += p[o * HH];
            } else {
                float f = ((word >> lane) & 1u) ? 1.f : 0.f;
                #pragma unroll
                for (int o = 0; o < OO; o++) acc[o] += f * p[o * HH];
            }
        }
        #pragma unroll
        for (int o = 0; o < OO; o++) {
            float v = acc[o];
            #pragma unroll
            for (int d = 16; d; d >>= 1) v += __shfl_xor_sync(0xffffffffu, v, d);
            if (lane == o) g_cur2[(size_t)m * OO + o] = v;
        }
    }
}

// ---------------------------------------------------------------------------
// Layer 2 scan per (b,o). blockDim 32 / grid 160 to spread over SMs.
// ---------------------------------------------------------------------------
__global__ void k_layer2(const float* __restrict__ thr2, float* __restrict__ out) {
    int idx = blockIdx.x * 32 + threadIdx.x;
    if (idx >= BB * OO) return;
    int o = idx % OO;

    float thr = thr2[o];
    float mem = 0.f, pre = 0.f, post = 0.f;
    bool  spk_prev = false;

    float* obase = out + 3 * SZ0 + 3 * SZ1 + idx;
    #pragma unroll 4
    for (int t = 0; t < TT; t++) {
        float cur = g_cur2[(size_t)t * BB * OO + idx];
        cur = cur > 0.f ? cur : 0.f;
        float base = BETA * mem + cur;
        mem = spk_prev ? 0.f : base;
        bool s = (mem - thr) > 0.f;
        spk_prev = s;
        float fs = s ? 1.f : 0.f;
        pre  = (pre  - DECAY * pre)  + A_PLUS  * fs;
        post = (post - DECAY * post) - A_MINUS * fs;

        size_t off = (size_t)t * BB * OO;
        obase[off]           = fs;
        obase[SZ2 + off]     = mem;
        obase[2 * SZ2 + off] = pre;
        obase[3 * SZ2 + off] = post;
    }
}

// ---------------------------------------------------------------------------
extern "C" void kernel_launch(void* const* d_in, const int* in_sizes, int n_in,
                              void* d_out, int out_size) {
    const float* x    = (const float*)d_in[0];
    const float* W1   = (const float*)d_in[1];
    const float* W2   = (const float*)d_in[2];
    const float* thr1 = (const float*)d_in[3];
    const float* thr2 = (const float*)d_in[4];
    float* out = (float*)d_out;

    k_s1    <<<128, 256>>>(W1);
    k_l0    <<<BB, 256>>>(x, out);
    k_l1    <<<BB, 256>>>(W1, thr1, out);
    k_cur2  <<<1600, 256>>>(W2);
    k_layer2<<<160, 32>>>(thr2, out);
}

// round 7
// speedup vs baseline: 1.3262x; 1.0467x over previous
#include <cuda_runtime.h>

#define TT 100
#define BB 512
#define NIN 784
#define HH 1024
#define OO 10

#define BETA    0.95f
#define DECAY   0.05f
#define A_PLUS  0.01f
#define A_MINUS 0.01f

#define MW0 25   // 784 bits -> 25 words (last word: 16 valid bits)
#define MW1 32   // 1024 bits -> 32 words

// Output layout (flattened tuple, each [T,B,dim] row-major):
// spk0, pre0, post0 | spk1, pre1, post1 | spk2, mem2, pre2, post2
#define SZ0 ((size_t)TT * BB * NIN)
#define SZ1 ((size_t)TT * BB * HH)
#define SZ2 ((size_t)TT * BB * OO)

// Scratch (no allocations allowed -> device globals)
__device__ unsigned int g_mask0[(size_t)TT * BB * MW0];  // [t][b][w]
__device__ unsigned int g_mask1[(size_t)TT * BB * MW1];  // [t][b][w] == [m][w]
__device__ float        g_S1[HH];
__device__ float        g_cur2[(size_t)TT * BB * OO];

// ---- packed f32x2 helpers (Blackwell) -------------------------------------
__device__ __forceinline__ unsigned long long packf2(float lo, float hi) {
    unsigned long long r;
    asm("mov.b64 %0, {%1, %2};" : "=l"(r) : "f"(lo), "f"(hi));
    return r;
}
__device__ __forceinline__ void unpackf2(unsigned long long v, float& lo, float& hi) {
    asm("mov.b64 {%0, %1}, %2;" : "=f"(lo), "=f"(hi) : "l"(v));
}
__device__ __forceinline__ unsigned long long fma2(unsigned long long a,
                                                   unsigned long long b,
                                                   unsigned long long c) {
    unsigned long long d;
    asm("fma.rn.f32x2 %0, %1, %2, %3;" : "=l"(d) : "l"(a), "l"(b), "l"(c));
    return d;
}
__device__ __forceinline__ unsigned long long add2(unsigned long long a,
                                                   unsigned long long b) {
    unsigned long long d;
    asm("add.rn.f32x2 %0, %1, %2;" : "=l"(d) : "l"(a), "l"(b));
    return d;
}

// Spread 8 bits of x into every 4th bit of a 32-bit word (Morton-4).
__device__ __forceinline__ unsigned int spread8(unsigned int x) {
    x &= 0xFFu;
    x = (x | (x << 12)) & 0x000F000Fu;
    x = (x | (x << 6))  & 0x03030303u;
    x = (x | (x << 3))  & 0x11111111u;
    return x;
}
// Pack 4 per-bit ballots into mask word j of this warp
// (bit h = 128*W + 32*j + 4*L' + k  <-  bit (8j+L') of bal_k).
__device__ __forceinline__ unsigned int pack_word(unsigned int b0, unsigned int b1,
                                                  unsigned int b2, unsigned int b3,
                                                  int j) {
    return  spread8(b0 >> (8 * j))
         | (spread8(b1 >> (8 * j)) << 1)
         | (spread8(b2 >> (8 * j)) << 2)
         | (spread8(b3 >> (8 * j)) << 3);
}

// ---------------------------------------------------------------------------
// S1[h] = sum_n W1[h,n]
// ---------------------------------------------------------------------------
__global__ void k_s1(const float* __restrict__ W1) {
    int h    = (blockIdx.x * blockDim.x + threadIdx.x) >> 5;
    int lane = threadIdx.x & 31;
    if (h >= HH) return;
    float s = 0.f;
    for (int n = lane; n < NIN; n += 32) s += W1[(size_t)h * NIN + n];
    #pragma unroll
    for (int d = 16; d; d >>= 1) s += __shfl_xor_sync(0xffffffffu, s, d);
    if (lane == 0) g_S1[h] = s;
}

// ---------------------------------------------------------------------------
// Layer 0, vectorized x4. One block per b. No shared mem, no barriers.
// ---------------------------------------------------------------------------
__global__ void __launch_bounds__(256)
k_l0(const float* __restrict__ x, float* __restrict__ out) {
    int b    = blockIdx.x;
    int tid  = threadIdx.x;
    int lane = tid & 31;
    int wrp  = tid >> 5;
    bool v0  = (tid < NIN / 4);          // 196 valid threads

    float4 mem = {0,0,0,0}, pre = {0,0,0,0}, post = {0,0,0,0};

    const float4* xp = (const float4*)(x + (size_t)b * NIN) + tid;
    float4* o_spk  = (float4*)(out + (size_t)b * NIN) + tid;
    float4* o_pre  = (float4*)(out + SZ0     + (size_t)b * NIN) + tid;
    float4* o_post = (float4*)(out + 2 * SZ0 + (size_t)b * NIN) + tid;
    unsigned int* mrow = g_mask0 + (size_t)b * MW0;

    const size_t xstride = (size_t)BB * NIN / 4;

    for (int t = 0; t < TT; t++) {
        float4 xv = {0,0,0,0};
        if (v0) xv = xp[t * xstride];
        mem.x = BETA * mem.x + xv.x;
        mem.y = BETA * mem.y + xv.y;
        mem.z = BETA * mem.z + xv.z;
        mem.w = BETA * mem.w + xv.w;
        bool s0 = v0 && (mem.x > 0.f);
        bool s1b = v0 && (mem.y > 0.f);
        bool s2 = v0 && (mem.z > 0.f);
        bool s3 = v0 && (mem.w > 0.f);

        unsigned int b0 = __ballot_sync(0xffffffffu, s0);
        unsigned int b1 = __ballot_sync(0xffffffffu, s1b);
        unsigned int b2 = __ballot_sync(0xffffffffu, s2);
        unsigned int b3 = __ballot_sync(0xffffffffu, s3);
        if (lane < 4) {
            int widx = wrp * 4 + lane;
            if (widx < MW0)
                mrow[(size_t)t * BB * MW0 + widx] = pack_word(b0, b1, b2, b3, lane);
        }

        if (v0) {
            float4 fs = {s0 ? 1.f : 0.f, s1b ? 1.f : 0.f, s2 ? 1.f : 0.f, s3 ? 1.f : 0.f};
            pre.x  = (pre.x  - DECAY * pre.x)  + A_PLUS  * fs.x;
            pre.y  = (pre.y  - DECAY * pre.y)  + A_PLUS  * fs.y;
            pre.z  = (pre.z  - DECAY * pre.z)  + A_PLUS  * fs.z;
            pre.w  = (pre.w  - DECAY * pre.w)  + A_PLUS  * fs.w;
            post.x = (post.x - DECAY * post.x) - A_MINUS * fs.x;
            post.y = (post.y - DECAY * post.y) - A_MINUS * fs.y;
            post.z = (post.z - DECAY * post.z) - A_MINUS * fs.z;
            post.w = (post.w - DECAY * post.w) - A_MINUS * fs.w;
            o_spk [t * xstride] = fs;
            o_pre [t * xstride] = pre;
            o_post[t * xstride] = post;
        }
    }
}

// ---------------------------------------------------------------------------
// Layer 1, vectorized x4. One block per b. No barriers: each warp re-derives
// the spk0 all-ones flag from g_mask0 (L2-resident). Fast path: cur1 = S1[h].
// ---------------------------------------------------------------------------
__global__ void __launch_bounds__(256)
k_l1(const float* __restrict__ W1,
     const float* __restrict__ thr1,
     float* __restrict__ out) {
    int b    = blockIdx.x;
    int tid  = threadIdx.x;
    int lane = tid & 31;
    int wrp  = tid >> 5;
    int h0   = tid * 4;

    float4 s1v = ((const float4*)g_S1)[tid];
    float4 thr = ((const float4*)thr1)[tid];
    float4 mem = {0,0,0,0}, pre = {0,0,0,0}, post = {0,0,0,0};
    bool sp0 = false, sp1 = false, sp2 = false, sp3 = false;

    float4* o_spk  = (float4*)(out + 3 * SZ0            + (size_t)b * HH) + tid;
    float4* o_pre  = (float4*)(out + 3 * SZ0 + SZ1      + (size_t)b * HH) + tid;
    float4* o_post = (float4*)(out + 3 * SZ0 + 2 * SZ1  + (size_t)b * HH) + tid;
    const unsigned int* m0 = g_mask0 + (size_t)b * MW0;
    unsigned int*      m1  = g_mask1 + (size_t)b * MW1;
    const size_t ostride = (size_t)BB * HH / 4;

    for (int t = 0; t < TT; t++) {
        unsigned int w  = 0xFFFFFFFFu;
        unsigned int vm = (lane == MW0 - 1) ? 0xFFFFu : 0xFFFFFFFFu;
        if (lane < MW0) w = __ldg(m0 + (size_t)t * BB * MW0 + lane);
        bool full = ((w & vm) == vm);
        bool allfull = (__ballot_sync(0xffffffffu, full) == 0xffffffffu);

        float4 cur = s1v;
        if (!allfull) {                          // rare path
            float c0 = 0.f, c1 = 0.f, c2 = 0.f, c3 = 0.f;
            #pragma unroll 1
            for (int wd = 0; wd < MW0; wd++) {
                unsigned int wv  = __shfl_sync(0xffffffffu, w, wd);
                unsigned int wvm = (wd == MW0 - 1) ? 0xFFFFu : 0xFFFFFFFFu;
                unsigned int z   = (~wv) & wvm;
                while (z) {
                    int bt = __ffs(z) - 1; z &= z - 1;
                    int n = wd * 32 + bt;
                    c0 += __ldg(W1 + (size_t)(h0 + 0) * NIN + n);
                    c1 += __ldg(W1 + (size_t)(h0 + 1) * NIN + n);
                    c2 += __ldg(W1 + (size_t)(h0 + 2) * NIN + n);
                    c3 += __ldg(W1 + (size_t)(h0 + 3) * NIN + n);
                }
            }
            cur.x -= c0; cur.y -= c1; cur.z -= c2; cur.w -= c3;
        }
        cur.x = cur.x > 0.f ? cur.x : 0.f;
        cur.y = cur.y > 0.f ? cur.y : 0.f;
        cur.z = cur.z > 0.f ? cur.z : 0.f;
        cur.w = cur.w > 0.f ? cur.w : 0.f;

        mem.x = sp0 ? 0.f : (BETA * mem.x + cur.x);
        mem.y = sp1 ? 0.f : (BETA * mem.y + cur.y);
        mem.z = sp2 ? 0.f : (BETA * mem.z + cur.z);
        mem.w = sp3 ? 0.f : (BETA * mem.w + cur.w);
        sp0 = (mem.x - thr.x) > 0.f;
        sp1 = (mem.y - thr.y) > 0.f;
        sp2 = (mem.z - thr.z) > 0.f;
        sp3 = (mem.w - thr.w) > 0.f;

        unsigned int b0 = __ballot_sync(0xffffffffu, sp0);
        unsigned int b1 = __ballot_sync(0xffffffffu, sp1);
        unsigned int b2 = __ballot_sync(0xffffffffu, sp2);
        unsigned int b3 = __ballot_sync(0xffffffffu, sp3);
        if (lane < 4)
            m1[(size_t)t * BB * MW1 + wrp * 4 + lane] = pack_word(b0, b1, b2, b3, lane);

        float4 fs = {sp0 ? 1.f : 0.f, sp1 ? 1.f : 0.f, sp2 ? 1.f : 0.f, sp3 ? 1.f : 0.f};
        pre.x  = (pre.x  - DECAY * pre.x)  + A_PLUS  * fs.x;
        pre.y  = (pre.y  - DECAY * pre.y)  + A_PLUS  * fs.y;
        pre.z  = (pre.z  - DECAY * pre.z)  + A_PLUS  * fs.z;
        pre.w  = (pre.w  - DECAY * pre.w)  + A_PLUS  * fs.w;
        post.x = (post.x - DECAY * post.x) - A_MINUS * fs.x;
        post.y = (post.y - DECAY * post.y) - A_MINUS * fs.y;
        post.z = (post.z - DECAY * post.z) - A_MINUS * fs.z;
        post.w = (post.w - DECAY * post.w) - A_MINUS * fs.w;

        o_spk [t * ostride] = fs;
        o_pre [t * ostride] = pre;
        o_post[t * ostride] = post;
    }
}

// ---------------------------------------------------------------------------
// cur2[m,o] = sum_{h: spk1[m,h]=1} W2[o,h].
// One warp handles RPW=8 rows at once: sW2 is loaded ONCE per (wd,o) and
// applied to 8 rows (LDS count /8 vs R6), accumulated in 4 f32x2 pairs with
// fma.rn.f32x2 (2 rows per FFMA -> FFMA pipe work /2).
// grid 800 x 8 warps x 8 rows = 51200 rows exactly.
// ---------------------------------------------------------------------------
#define RPW 8
__global__ void __launch_bounds__(256)
k_cur2(const float* __restrict__ W2) {
    __shared__ float sW2[OO * HH];   // 40 KB, o-major
    for (int i = threadIdx.x; i < OO * HH; i += 256) sW2[i] = W2[i];
    __syncthreads();

    int wid  = threadIdx.x >> 5;
    int lane = threadIdx.x & 31;
    int m0   = (blockIdx.x * 8 + wid) * RPW;

    unsigned int mw[RPW];                 // lane holds word `lane` of each row
    #pragma unroll
    for (int r = 0; r < RPW; r++)
        mw[r] = g_mask1[(size_t)(m0 + r) * MW1 + lane];

    unsigned long long acc[RPW / 2][OO];  // pair p = rows (2p, 2p+1)
    #pragma unroll
    for (int p = 0; p < RPW / 2; p++)
        #pragma unroll
        for (int o = 0; o < OO; o++) acc[p][o] = 0ull;

    #pragma unroll 4
    for (int wd = 0; wd < MW1; wd++) {
        unsigned long long sp[RPW / 2];
        #pragma unroll
        for (int p = 0; p < RPW / 2; p++) {
            unsigned int w0 = __shfl_sync(0xffffffffu, mw[2 * p],     wd);
            unsigned int w1 = __shfl_sync(0xffffffffu, mw[2 * p + 1], wd);
            float f0 = ((w0 >> lane) & 1u) ? 1.f : 0.f;
            float f1 = ((w1 >> lane) & 1u) ? 1.f : 0.f;
            sp[p] = packf2(f0, f1);
        }
        const float* pw = &sW2[wd * 32 + lane];   // lane-stride 1: conflict-free
        #pragma unroll
        for (int o = 0; o < OO; o++) {
            float wv = pw[o * HH];
            unsigned long long bb = packf2(wv, wv);
            #pragma unroll
            for (int p = 0; p < RPW / 2; p++)
                acc[p][o] = fma2(sp[p], bb, acc[p][o]);
        }
    }

    // butterfly reduce across lanes (every lane ends with the totals)
    #pragma unroll
    for (int p = 0; p < RPW / 2; p++)
        #pragma unroll
        for (int o = 0; o < OO; o++)
            #pragma unroll
            for (int d = 16; d; d >>= 1) {
                unsigned long long v = __shfl_xor_sync(0xffffffffu, acc[p][o], d);
                acc[p][o] = add2(acc[p][o], v);
            }

    if (lane < RPW) {                  // lane r writes row m0+r
        int p  = lane >> 1;
        int hi = lane & 1;
        float* dst = g_cur2 + (size_t)(m0 + lane) * OO;
        #pragma unroll
        for (int o = 0; o < OO; o++) {
            float lo, hv; unpackf2(acc[p][o], lo, hv);
            dst[o] = hi ? hv : lo;
        }
    }
}

// ---------------------------------------------------------------------------
// Layer 2 scan per (b,o).
// ---------------------------------------------------------------------------
__global__ void k_layer2(const float* __restrict__ thr2, float* __restrict__ out) {
    int idx = blockIdx.x * 32 + threadIdx.x;
    if (idx >= BB * OO) return;
    int o = idx % OO;

    float thr = thr2[o];
    float mem = 0.f, pre = 0.f, post = 0.f;
    bool  spk_prev = false;

    float* obase = out + 3 * SZ0 + 3 * SZ1 + idx;
    #pragma unroll 4
    for (int t = 0; t < TT; t++) {
        float cur = g_cur2[(size_t)t * BB * OO + idx];
        cur = cur > 0.f ? cur : 0.f;
        float base = BETA * mem + cur;
        mem = spk_prev ? 0.f : base;
        bool s = (mem - thr) > 0.f;
        spk_prev = s;
        float fs = s ? 1.f : 0.f;
        pre  = (pre  - DECAY * pre)  + A_PLUS  * fs;
        post = (post - DECAY * post) - A_MINUS * fs;

        size_t off = (size_t)t * BB * OO;
        obase[off]           = fs;
        obase[SZ2 + off]     = mem;
        obase[2 * SZ2 + off] = pre;
        obase[3 * SZ2 + off] = post;
    }
}

// ---------------------------------------------------------------------------
extern "C" void kernel_launch(void* const* d_in, const int* in_sizes, int n_in,
                              void* d_out, int out_size) {
    const float* x    = (const float*)d_in[0];
    const float* W1   = (const float*)d_in[1];
    const float* W2   = (const float*)d_in[2];
    const float* thr1 = (const float*)d_in[3];
    const float* thr2 = (const float*)d_in[4];
    float* out = (float*)d_out;

    k_s1    <<<128, 256>>>(W1);
    k_l0    <<<BB, 256>>>(x, out);
    k_l1    <<<BB, 256>>>(W1, thr1, out);
    k_cur2  <<<800, 256>>>(W2);
    k_layer2<<<160, 32>>>(thr2, out);
}

// round 8
// speedup vs baseline: 1.4809x; 1.1167x over previous
#include <cuda_runtime.h>

#define TT 100
#define BB 512
#define NIN 784
#define HH 1024
#define OO 10

#define BETA    0.95f
#define DECAY   0.05f
#define A_PLUS  0.01f
#define A_MINUS 0.01f

#define MW0 25   // 784 bits -> 25 words (last word: 16 valid bits)
#define MW1 32   // 1024 bits -> 32 words

// Output layout (flattened tuple, each [T,B,dim] row-major):
// spk0, pre0, post0 | spk1, pre1, post1 | spk2, mem2, pre2, post2
#define SZ0 ((size_t)TT * BB * NIN)
#define SZ1 ((size_t)TT * BB * HH)
#define SZ2 ((size_t)TT * BB * OO)

// Scratch (no allocations allowed -> device globals)
__device__ unsigned int g_mask1[(size_t)TT * BB * MW1];  // [m][w], m = t*BB+b
__device__ float        g_S1[HH];
__device__ float        g_cur2[(size_t)TT * BB * OO];

// ---- packed f32x2 helpers (Blackwell) -------------------------------------
__device__ __forceinline__ unsigned long long packf2(float lo, float hi) {
    unsigned long long r;
    asm("mov.b64 %0, {%1, %2};" : "=l"(r) : "f"(lo), "f"(hi));
    return r;
}
__device__ __forceinline__ void unpackf2(unsigned long long v, float& lo, float& hi) {
    asm("mov.b64 {%0, %1}, %2;" : "=f"(lo), "=f"(hi) : "l"(v));
}
__device__ __forceinline__ unsigned long long fma2(unsigned long long a,
                                                   unsigned long long b,
                                                   unsigned long long c) {
    unsigned long long d;
    asm("fma.rn.f32x2 %0, %1, %2, %3;" : "=l"(d) : "l"(a), "l"(b), "l"(c));
    return d;
}

// Spread 8 bits of x into every 4th bit of a 32-bit word (Morton-4).
__device__ __forceinline__ unsigned int spread8(unsigned int x) {
    x &= 0xFFu;
    x = (x | (x << 12)) & 0x000F000Fu;
    x = (x | (x << 6))  & 0x03030303u;
    x = (x | (x << 3))  & 0x11111111u;
    return x;
}
// Pack 4 per-bit ballots into mask word j of this warp
// (bit h = 128*W + 32*j + 4*L' + k  <-  bit (8j+L') of bal_k).
__device__ __forceinline__ unsigned int pack_word(unsigned int b0, unsigned int b1,
                                                  unsigned int b2, unsigned int b3,
                                                  int j) {
    return  spread8(b0 >> (8 * j))
         | (spread8(b1 >> (8 * j)) << 1)
         | (spread8(b2 >> (8 * j)) << 2)
         | (spread8(b3 >> (8 * j)) << 3);
}

// ---------------------------------------------------------------------------
// S1[h] = sum_n W1[h,n]
// ---------------------------------------------------------------------------
__global__ void k_s1(const float* __restrict__ W1) {
    int h    = (blockIdx.x * blockDim.x + threadIdx.x) >> 5;
    int lane = threadIdx.x & 31;
    if (h >= HH) return;
    float s = 0.f;
    for (int n = lane; n < NIN; n += 32) s += W1[(size_t)h * NIN + n];
    #pragma unroll
    for (int d = 16; d; d >>= 1) s += __shfl_xor_sync(0xffffffffu, s, d);
    if (lane == 0) g_S1[h] = s;
}

// ---------------------------------------------------------------------------
// Fused layer0 + layer1, ONE barrier total. Block = batch element b, 256 thr.
// Phase 0: layer-0 scan (x4 vectorized), spk0 masks -> SMEM (all T).
// Phase 1: layer-1 scan (x4 vectorized), masks read from SMEM, no barriers.
// ---------------------------------------------------------------------------
__global__ void __launch_bounds__(256, 4)
k_l01(const float* __restrict__ x,
      const float* __restrict__ W1,
      const float* __restrict__ thr1,
      float* __restrict__ out) {
    __shared__ unsigned int sm0[TT * MW0];   // 10 KB: [t][w]

    int b    = blockIdx.x;
    int tid  = threadIdx.x;
    int lane = tid & 31;
    int wrp  = tid >> 5;

    // ======== phase 0: layer 0 ========
    {
        bool v0 = (tid < NIN / 4);           // 196 valid float4 threads
        float4 mem = {0,0,0,0}, pre = {0,0,0,0}, post = {0,0,0,0};

        const float4* xp = (const float4*)(x + (size_t)b * NIN) + tid;
        float4* o_spk  = (float4*)(out + (size_t)b * NIN) + tid;
        float4* o_pre  = (float4*)(out + SZ0     + (size_t)b * NIN) + tid;
        float4* o_post = (float4*)(out + 2 * SZ0 + (size_t)b * NIN) + tid;
        const size_t xstride = (size_t)BB * NIN / 4;

        for (int t = 0; t < TT; t++) {
            float4 xv = {0,0,0,0};
            if (v0) xv = xp[t * xstride];
            mem.x = BETA * mem.x + xv.x;
            mem.y = BETA * mem.y + xv.y;
            mem.z = BETA * mem.z + xv.z;
            mem.w = BETA * mem.w + xv.w;
            bool s0 = v0 && (mem.x > 0.f);
            bool s1b = v0 && (mem.y > 0.f);
            bool s2 = v0 && (mem.z > 0.f);
            bool s3 = v0 && (mem.w > 0.f);

            unsigned int b0 = __ballot_sync(0xffffffffu, s0);
            unsigned int b1 = __ballot_sync(0xffffffffu, s1b);
            unsigned int b2 = __ballot_sync(0xffffffffu, s2);
            unsigned int b3 = __ballot_sync(0xffffffffu, s3);
            if (lane < 4) {
                int widx = wrp * 4 + lane;
                if (widx < MW0)
                    sm0[t * MW0 + widx] = pack_word(b0, b1, b2, b3, lane);
            }

            if (v0) {
                float4 fs = {s0 ? 1.f : 0.f, s1b ? 1.f : 0.f, s2 ? 1.f : 0.f, s3 ? 1.f : 0.f};
                pre.x  = (pre.x  - DECAY * pre.x)  + A_PLUS  * fs.x;
                pre.y  = (pre.y  - DECAY * pre.y)  + A_PLUS  * fs.y;
                pre.z  = (pre.z  - DECAY * pre.z)  + A_PLUS  * fs.z;
                pre.w  = (pre.w  - DECAY * pre.w)  + A_PLUS  * fs.w;
                post.x = (post.x - DECAY * post.x) - A_MINUS * fs.x;
                post.y = (post.y - DECAY * post.y) - A_MINUS * fs.y;
                post.z = (post.z - DECAY * post.z) - A_MINUS * fs.z;
                post.w = (post.w - DECAY * post.w) - A_MINUS * fs.w;
                o_spk [t * xstride] = fs;
                o_pre [t * xstride] = pre;
                o_post[t * xstride] = post;
            }
        }
    }

    __syncthreads();   // the ONLY barrier

    // ======== phase 1: layer 1 ========
    {
        int h0 = tid * 4;
        float4 s1v = ((const float4*)g_S1)[tid];
        float4 thr = ((const float4*)thr1)[tid];
        float4 mem = {0,0,0,0}, pre = {0,0,0,0}, post = {0,0,0,0};
        bool sp0 = false, sp1 = false, sp2 = false, sp3 = false;

        float4* o_spk  = (float4*)(out + 3 * SZ0            + (size_t)b * HH) + tid;
        float4* o_pre  = (float4*)(out + 3 * SZ0 + SZ1      + (size_t)b * HH) + tid;
        float4* o_post = (float4*)(out + 3 * SZ0 + 2 * SZ1  + (size_t)b * HH) + tid;
        unsigned int* m1 = g_mask1 + (size_t)b * MW1;
        const size_t ostride = (size_t)BB * HH / 4;

        for (int t = 0; t < TT; t++) {
            unsigned int w  = 0xFFFFFFFFu;
            unsigned int vm = (lane == MW0 - 1) ? 0xFFFFu : 0xFFFFFFFFu;
            if (lane < MW0) w = sm0[t * MW0 + lane];
            bool full = ((w & vm) == vm);
            bool allfull = (__ballot_sync(0xffffffffu, full) == 0xffffffffu);

            float4 cur = s1v;
            if (!allfull) {                          // rare path
                float c0 = 0.f, c1 = 0.f, c2 = 0.f, c3 = 0.f;
                #pragma unroll 1
                for (int wd = 0; wd < MW0; wd++) {
                    unsigned int wv  = __shfl_sync(0xffffffffu, w, wd);
                    unsigned int wvm = (wd == MW0 - 1) ? 0xFFFFu : 0xFFFFFFFFu;
                    unsigned int z   = (~wv) & wvm;
                    while (z) {
                        int bt = __ffs(z) - 1; z &= z - 1;
                        int n = wd * 32 + bt;
                        c0 += __ldg(W1 + (size_t)(h0 + 0) * NIN + n);
                        c1 += __ldg(W1 + (size_t)(h0 + 1) * NIN + n);
                        c2 += __ldg(W1 + (size_t)(h0 + 2) * NIN + n);
                        c3 += __ldg(W1 + (size_t)(h0 + 3) * NIN + n);
                    }
                }
                cur.x -= c0; cur.y -= c1; cur.z -= c2; cur.w -= c3;
            }
            cur.x = cur.x > 0.f ? cur.x : 0.f;
            cur.y = cur.y > 0.f ? cur.y : 0.f;
            cur.z = cur.z > 0.f ? cur.z : 0.f;
            cur.w = cur.w > 0.f ? cur.w : 0.f;

            mem.x = sp0 ? 0.f : (BETA * mem.x + cur.x);
            mem.y = sp1 ? 0.f : (BETA * mem.y + cur.y);
            mem.z = sp2 ? 0.f : (BETA * mem.z + cur.z);
            mem.w = sp3 ? 0.f : (BETA * mem.w + cur.w);
            sp0 = (mem.x - thr.x) > 0.f;
            sp1 = (mem.y - thr.y) > 0.f;
            sp2 = (mem.z - thr.z) > 0.f;
            sp3 = (mem.w - thr.w) > 0.f;

            unsigned int b0 = __ballot_sync(0xffffffffu, sp0);
            unsigned int b1 = __ballot_sync(0xffffffffu, sp1);
            unsigned int b2 = __ballot_sync(0xffffffffu, sp2);
            unsigned int b3 = __ballot_sync(0xffffffffu, sp3);
            if (lane < 4)
                m1[(size_t)t * BB * MW1 + wrp * 4 + lane] = pack_word(b0, b1, b2, b3, lane);

            float4 fs = {sp0 ? 1.f : 0.f, sp1 ? 1.f : 0.f, sp2 ? 1.f : 0.f, sp3 ? 1.f : 0.f};
            pre.x  = (pre.x  - DECAY * pre.x)  + A_PLUS  * fs.x;
            pre.y  = (pre.y  - DECAY * pre.y)  + A_PLUS  * fs.y;
            pre.z  = (pre.z  - DECAY * pre.z)  + A_PLUS  * fs.z;
            pre.w  = (pre.w  - DECAY * pre.w)  + A_PLUS  * fs.w;
            post.x = (post.x - DECAY * post.x) - A_MINUS * fs.x;
            post.y = (post.y - DECAY * post.y) - A_MINUS * fs.y;
            post.z = (post.z - DECAY * post.z) - A_MINUS * fs.z;
            post.w = (post.w - DECAY * post.w) - A_MINUS * fs.w;

            o_spk [t * ostride] = fs;
            o_pre [t * ostride] = pre;
            o_post[t * ostride] = post;
        }
    }
}

// ---------------------------------------------------------------------------
// cur2[m,o] = sum_{h: spk1[m,h]=1} W2[o,h].
// Lane-owns-row design: each lane owns RPL=2 complete rows; no shfl, no
// butterfly. W2 staged in SMEM as output-pairs (float2, broadcast LDS.64).
// fma2 packs the o-pair. Each lane writes its rows directly.
// Groups of 64 rows per warp; 800 groups; grid 148 x 8 warps, g = w*148+blk
// so active warps spread evenly across SMs (5-6 per block).
// ---------------------------------------------------------------------------
#define RPL 2
#define NGRP ((TT * BB) / (32 * RPL))    // 800
__global__ void __launch_bounds__(256)
k_cur2(const float* __restrict__ W2) {
    __shared__ float2 sW2p[HH * (OO / 2)];   // 40 KB: [h][p]
    for (int i = threadIdx.x; i < HH * (OO / 2); i += 256) {
        int h = i / (OO / 2), p = i % (OO / 2);
        sW2p[i] = make_float2(W2[(size_t)(2 * p) * HH + h],
                              W2[(size_t)(2 * p + 1) * HH + h]);
    }
    __syncthreads();

    int w    = threadIdx.x >> 5;
    int lane = threadIdx.x & 31;
    int g    = w * 148 + blockIdx.x;
    if (g >= NGRP) return;
    int m0 = g * (32 * RPL) + lane * RPL;    // 2 consecutive rows for this lane

    const uint4* r0 = (const uint4*)(g_mask1 + (size_t)m0 * MW1);
    const uint4* r1 = (const uint4*)(g_mask1 + (size_t)(m0 + 1) * MW1);

    unsigned long long acc0[OO / 2], acc1[OO / 2];
    #pragma unroll
    for (int p = 0; p < OO / 2; p++) { acc0[p] = 0ull; acc1[p] = 0ull; }

    #pragma unroll 1
    for (int c = 0; c < 8; c++) {            // 4 words per chunk
        uint4 wa = r0[c], wb = r1[c];
        #pragma unroll
        for (int j = 0; j < 4; j++) {
            unsigned int u0 = (j == 0) ? wa.x : (j == 1) ? wa.y : (j == 2) ? wa.z : wa.w;
            unsigned int u1 = (j == 0) ? wb.x : (j == 1) ? wb.y : (j == 2) ? wb.z : wb.w;
            const float2* bp = &sW2p[(c * 128 + j * 32) * (OO / 2)];
            #pragma unroll 8
            for (int k = 0; k < 32; k++) {
                float f0 = ((u0 >> k) & 1u) ? 1.f : 0.f;
                float f1 = ((u1 >> k) & 1u) ? 1.f : 0.f;
                unsigned long long a0 = packf2(f0, f0);
                unsigned long long a1 = packf2(f1, f1);
                #pragma unroll
                for (int p = 0; p < OO / 2; p++) {
                    float2 bv = bp[k * (OO / 2) + p];
                    unsigned long long bb = packf2(bv.x, bv.y);
                    acc0[p] = fma2(a0, bb, acc0[p]);
                    acc1[p] = fma2(a1, bb, acc1[p]);
                }
            }
        }
    }

    float* d0 = g_cur2 + (size_t)m0 * OO;
    float* d1 = d0 + OO;
    #pragma unroll
    for (int p = 0; p < OO / 2; p++) {
        float lo, hi;
        unpackf2(acc0[p], lo, hi); d0[2 * p] = lo; d0[2 * p + 1] = hi;
        unpackf2(acc1[p], lo, hi); d1[2 * p] = lo; d1[2 * p + 1] = hi;
    }
}

// ---------------------------------------------------------------------------
// Layer 2 scan per (b,o).
// ---------------------------------------------------------------------------
__global__ void k_layer2(const float* __restrict__ thr2, float* __restrict__ out) {
    int idx = blockIdx.x * 32 + threadIdx.x;
    if (idx >= BB * OO) return;
    int o = idx % OO;

    float thr = thr2[o];
    float mem = 0.f, pre = 0.f, post = 0.f;
    bool  spk_prev = false;

    float* obase = out + 3 * SZ0 + 3 * SZ1 + idx;
    #pragma unroll 4
    for (int t = 0; t < TT; t++) {
        float cur = g_cur2[(size_t)t * BB * OO + idx];
        cur = cur > 0.f ? cur : 0.f;
        float base = BETA * mem + cur;
        mem = spk_prev ? 0.f : base;
        bool s = (mem - thr) > 0.f;
        spk_prev = s;
        float fs = s ? 1.f : 0.f;
        pre  = (pre  - DECAY * pre)  + A_PLUS  * fs;
        post = (post - DECAY * post) - A_MINUS * fs;

        size_t off = (size_t)t * BB * OO;
        obase[off]           = fs;
        obase[SZ2 + off]     = mem;
        obase[2 * SZ2 + off] = pre;
        obase[3 * SZ2 + off] = post;
    }
}

// ---------------------------------------------------------------------------
extern "C" void kernel_launch(void* const* d_in, const int* in_sizes, int n_in,
                              void* d_out, int out_size) {
    const float* x    = (const float*)d_in[0];
    const float* W1   = (const float*)d_in[1];
    const float* W2   = (const float*)d_in[2];
    const float* thr1 = (const float*)d_in[3];
    const float* thr2 = (const float*)d_in[4];
    float* out = (float*)d_out;

    k_s1    <<<128, 256>>>(W1);
    k_l01   <<<BB, 256>>>(x, W1, thr1, out);
    k_cur2  <<<148, 256>>>(W2);
    k_layer2<<<160, 32>>>(thr2, out);
}